// round 3
// baseline (speedup 1.0000x reference)
#include <cuda_runtime.h>

// Sparse ConvTranspose3d on GB300 (sm_103a)
//   out[r,:] = bias + sum_{(k,n): out_index[k,n]==r} feats[n,:] @ weight[k,:,:]^T
//
// Kernel 1: out = bias broadcast (float4 stores, HBM write floor).
// Kernel 2: persistent-over-k tile kernel. Block = 128-point tile x KCHUNK=9 offsets.
//   - A (128x64) loaded once into SMEM
//   - W[k] double-buffered in SMEM via cp.async (prefetch k+1 during compute of k)
//   - 8x8 register microtile per thread (128 thr): FFMA:LDS.128 = 16:1
//   - scatter epilogue: red.global.add.v4.f32 (overlaps with next k's FFMA)

#define CIN    64
#define COUT   64
#define TILE_N 128
#define KCHUNK 9

__global__ void bias_init_kernel(float4* __restrict__ out4,
                                 const float4* __restrict__ bias4,
                                 int total4) {
    int i = blockIdx.x * blockDim.x + threadIdx.x;
    if (i < total4) {
        out4[i] = bias4[i & 15];   // 64 floats per row = 16 float4 chunks
    }
}

__global__ void __launch_bounds__(128, 3) spconvt_gemm_scatter_kernel(
    const float* __restrict__ feats,     // [N, CIN]
    const float* __restrict__ weight,    // [KV, COUT, CIN]
    const int*   __restrict__ out_index, // [KV, N]
    float*       __restrict__ out,       // [n_out, COUT]
    int N, int KV)
{
    extern __shared__ float smem[];
    float (*As)[CIN] = reinterpret_cast<float (*)[CIN]>(smem);   // 128x64 = 32KB
    float* Wbuf = smem + TILE_N * CIN;                            // 2 x (64x64) = 32KB

    const int tid = threadIdx.x;
    const int n0  = blockIdx.x * TILE_N;
    const int k0  = blockIdx.y * KCHUNK;

    // ---- Load A tile once: 128 rows x 16 float4, coalesced, zero-pad past N ----
    const float4* f4 = reinterpret_cast<const float4*>(feats);
    #pragma unroll
    for (int t = 0; t < 16; t++) {
        int idx = tid + t * 128;          // 0..2047
        int p = idx >> 4;
        int q = idx & 15;
        int n = n0 + p;
        float4 v = make_float4(0.f, 0.f, 0.f, 0.f);
        if (n < N) v = f4[(size_t)n * 16 + q];
        *reinterpret_cast<float4*>(&As[p][q * 4]) = v;
    }

    // ---- cp.async loader for W[k] into buffer `b`, chunk-swizzled ----
    auto cpW = [&](int k, int b) {
        const char* src = reinterpret_cast<const char*>(weight + (size_t)k * COUT * CIN);
        float* dstbase = Wbuf + b * COUT * CIN;
        #pragma unroll
        for (int j = 0; j < 8; j++) {
            int idx = tid + 128 * j;      // 0..1023 float4s
            int c = idx >> 4;
            int q = idx & 15;
            int qs = q ^ ((c >> 3) & 7);  // phys chunk swizzle
            unsigned dst = (unsigned)__cvta_generic_to_shared(dstbase + c * CIN + qs * 4);
            asm volatile("cp.async.cg.shared.global [%0], [%1], 16;\n"
                         :: "r"(dst), "l"(src + (size_t)idx * 16));
        }
        asm volatile("cp.async.commit_group;\n");
    };

    cpW(k0, 0);
    asm volatile("cp.async.wait_group 0;\n" ::: "memory");
    __syncthreads();   // A + W[k0] visible

    const int tc = tid & 7;
    const int tp = tid >> 3;
    const int c0 = tc * 8;
    const int p0 = tp * 8;

    int buf = 0;
    for (int kk = 0; kk < KCHUNK; kk++) {
        int k = k0 + kk;
        if (k >= KV) break;

        // prefetch next W while we compute this one
        if (kk + 1 < KCHUNK && k + 1 < KV) cpW(k + 1, buf ^ 1);

        // prefetch output row ids
        int rr[8];
        const int* oi = out_index + (size_t)k * N + n0 + p0;
        #pragma unroll
        for (int pj = 0; pj < 8; pj++)
            rr[pj] = (n0 + p0 + pj < N) ? oi[pj] : -1;

        const float* Wc = Wbuf + buf * COUT * CIN;

        float acc[8][8];
        #pragma unroll
        for (int a = 0; a < 8; a++)
            #pragma unroll
            for (int b2 = 0; b2 < 8; b2++) acc[a][b2] = 0.f;

        #pragma unroll 2
        for (int q = 0; q < 16; q++) {       // CIN in 16B chunks
            float4 av[8];
            #pragma unroll
            for (int j = 0; j < 8; j++)
                av[j] = *reinterpret_cast<const float4*>(&As[p0 + j][q * 4]);

            int qs = q ^ tc;                  // (c0+cj)>>3 == tc
            #pragma unroll
            for (int cj = 0; cj < 8; cj++) {
                float4 wv = *reinterpret_cast<const float4*>(&Wc[(c0 + cj) * CIN + qs * 4]);
                #pragma unroll
                for (int pj = 0; pj < 8; pj++) {
                    acc[pj][cj] += av[pj].x * wv.x;
                    acc[pj][cj] += av[pj].y * wv.y;
                    acc[pj][cj] += av[pj].z * wv.z;
                    acc[pj][cj] += av[pj].w * wv.w;
                }
            }
        }

        // ---- Scatter epilogue: fire-and-forget vector reductions ----
        #pragma unroll
        for (int pj = 0; pj < 8; pj++) {
            if (rr[pj] >= 0) {
                float* dst = out + (size_t)rr[pj] * COUT + c0;   // 16B aligned
                asm volatile("red.global.add.v4.f32 [%0], {%1, %2, %3, %4};"
                             :: "l"(dst),
                                "f"(acc[pj][0]), "f"(acc[pj][1]),
                                "f"(acc[pj][2]), "f"(acc[pj][3])
                             : "memory");
                asm volatile("red.global.add.v4.f32 [%0], {%1, %2, %3, %4};"
                             :: "l"(dst + 4),
                                "f"(acc[pj][4]), "f"(acc[pj][5]),
                                "f"(acc[pj][6]), "f"(acc[pj][7])
                             : "memory");
            }
        }

        asm volatile("cp.async.wait_group 0;\n" ::: "memory");
        __syncthreads();      // everyone done reading Wbuf[buf]; next W ready
        buf ^= 1;
    }
}

extern "C" void kernel_launch(void* const* d_in, const int* in_sizes, int n_in,
                              void* d_out, int out_size) {
    const float* feats     = (const float*)d_in[0];   // [N, 64]
    const float* weight    = (const float*)d_in[1];   // [KV, 64, 64]
    const float* bias      = (const float*)d_in[2];   // [64]
    const int*   out_index = (const int*)d_in[3];     // [KV, N]
    float* out = (float*)d_out;                        // [n_out, 64]

    int N  = in_sizes[0] / CIN;
    int KV = in_sizes[1] / (COUT * CIN);

    // 1) out = bias (broadcast)
    int total4 = out_size / 4;
    int ib = (total4 + 255) / 256;
    bias_init_kernel<<<ib, 256>>>((float4*)out, (const float4*)bias, total4);

    // 2) persistent-over-k GEMM + scatter-add
    const int smem_bytes = (TILE_N * CIN + 2 * COUT * CIN) * sizeof(float);  // 64KB
    cudaFuncSetAttribute(spconvt_gemm_scatter_kernel,
                         cudaFuncAttributeMaxDynamicSharedMemorySize, smem_bytes);
    dim3 grid((N + TILE_N - 1) / TILE_N, (KV + KCHUNK - 1) / KCHUNK);
    spconvt_gemm_scatter_kernel<<<grid, 128, smem_bytes>>>(
        feats, weight, out_index, out, N, KV);
}

// round 4
// speedup vs baseline: 1.0174x; 1.0174x over previous
#include <cuda_runtime.h>

// Sparse ConvTranspose3d on GB300 (sm_103a)
//   out[r,:] = bias + sum_{(k,n): out_index[k,n]==r} feats[n,:] @ weight[k,:,:]^T
//
// Kernel 1: out = bias broadcast (HBM write floor).
// Kernel 2: persistent-over-k tile kernel, fma.rn.f32x2 mainloop.
//   - lane-split K-reduction: f32x2 lo lane accumulates even cin, hi lane odd cin
//     -> both operands load pre-packed from SMEM (no pack instrs), fold lo+hi at end
//   - 256 threads, 8pt x 4ch microtile, 2 blocks/SM
//   - W[k] double-buffered via cp.async; A tile loaded once per block
//   - scatter epilogue: red.global.add.v4.f32

#define CIN    64
#define COUT   64
#define TILE_N 128
#define KCHUNK 9

__global__ void bias_init_kernel(float4* __restrict__ out4,
                                 const float4* __restrict__ bias4,
                                 int total4) {
    int i = blockIdx.x * blockDim.x + threadIdx.x;
    if (i < total4) {
        out4[i] = bias4[i & 15];   // 64 floats per row = 16 float4 chunks
    }
}

__device__ __forceinline__ void fma2(double& d, double a, double b) {
    asm("fma.rn.f32x2 %0, %1, %2, %0;" : "+l"(*(unsigned long long*)&d)
        : "l"(*(unsigned long long*)&a), "l"(*(unsigned long long*)&b));
}

__global__ void __launch_bounds__(256, 2) spconvt_gemm_scatter_kernel(
    const float* __restrict__ feats,     // [N, CIN]
    const float* __restrict__ weight,    // [KV, COUT, CIN]
    const int*   __restrict__ out_index, // [KV, N]
    float*       __restrict__ out,       // [n_out, COUT]
    int N, int KV)
{
    extern __shared__ float smem[];
    float (*As)[CIN] = reinterpret_cast<float (*)[CIN]>(smem);   // 128x64 = 32KB
    float* Wbuf = smem + TILE_N * CIN;                            // 2 x (64x64) = 32KB

    const int tid = threadIdx.x;
    const int n0  = blockIdx.x * TILE_N;
    const int k0  = blockIdx.y * KCHUNK;

    // ---- Load A tile once: 2048 float4, 8 iters over 256 threads ----
    const float4* f4 = reinterpret_cast<const float4*>(feats);
    #pragma unroll
    for (int t = 0; t < 8; t++) {
        int idx = tid + t * 256;          // 0..2047
        int p = idx >> 4;
        int q = idx & 15;
        int n = n0 + p;
        float4 v = make_float4(0.f, 0.f, 0.f, 0.f);
        if (n < N) v = f4[(size_t)n * 16 + q];
        *reinterpret_cast<float4*>(&As[p][q * 4]) = v;
    }

    // ---- cp.async loader for W[k] into buffer b, chunk-swizzled ----
    // phys chunk = q ^ ((c>>2) & 15); reader uses qs = q ^ tc with tc = c>>2
    auto cpW = [&](int k, int b) {
        const char* src = reinterpret_cast<const char*>(weight + (size_t)k * COUT * CIN);
        float* dstbase = Wbuf + b * COUT * CIN;
        #pragma unroll
        for (int j = 0; j < 4; j++) {
            int idx = tid + 256 * j;      // 0..1023 float4s
            int c = idx >> 4;
            int q = idx & 15;
            int qs = q ^ ((c >> 2) & 15);
            unsigned dst = (unsigned)__cvta_generic_to_shared(dstbase + c * CIN + qs * 4);
            asm volatile("cp.async.cg.shared.global [%0], [%1], 16;\n"
                         :: "r"(dst), "l"(src + (size_t)idx * 16));
        }
        asm volatile("cp.async.commit_group;\n");
    };

    cpW(k0, 0);
    asm volatile("cp.async.wait_group 0;\n" ::: "memory");
    __syncthreads();   // A + W[k0] visible

    // microtile: 16 channel-groups (4ch) x 32 point-groups? no:
    // tc in [0,16): channels c0 = 4*tc; tp in [0,16): points p0 = 8*tp
    const int tc = tid & 15;
    const int tp = tid >> 4;
    const int c0 = tc * 4;
    const int p0 = tp * 8;

    int buf = 0;
    for (int kk = 0; kk < KCHUNK; kk++) {
        int k = k0 + kk;
        if (k >= KV) break;

        // prefetch next W while computing this one
        if (kk + 1 < KCHUNK && k + 1 < KV) cpW(k + 1, buf ^ 1);

        // prefetch output row ids
        int rr[8];
        const int* oi = out_index + (size_t)k * N + n0 + p0;
        #pragma unroll
        for (int pj = 0; pj < 8; pj++)
            rr[pj] = (n0 + p0 + pj < N) ? oi[pj] : -1;

        const float* Wc = Wbuf + buf * COUT * CIN;

        // packed accumulators: lo lane = even-cin partial, hi lane = odd-cin partial
        double acc2[8][4];
        #pragma unroll
        for (int a = 0; a < 8; a++)
            #pragma unroll
            for (int b2 = 0; b2 < 4; b2++) acc2[a][b2] = 0.0;

        const int qsx = tc;
        #pragma unroll 4
        for (int q = 0; q < 16; q++) {       // CIN in 16B chunks (4 cin = 2 packed steps)
            int qs = q ^ qsx;
            double2 wv[4];
            #pragma unroll
            for (int cj = 0; cj < 4; cj++)
                wv[cj] = *reinterpret_cast<const double2*>(&Wc[(c0 + cj) * CIN + qs * 4]);

            #pragma unroll
            for (int pj = 0; pj < 8; pj++) {
                double2 av = *reinterpret_cast<const double2*>(&As[p0 + pj][q * 4]);
                #pragma unroll
                for (int cj = 0; cj < 4; cj++) {
                    fma2(acc2[pj][cj], av.x, wv[cj].x);
                    fma2(acc2[pj][cj], av.y, wv[cj].y);
                }
            }
        }

        // ---- fold lanes + scatter ----
        #pragma unroll
        for (int pj = 0; pj < 8; pj++) {
            if (rr[pj] >= 0) {
                float r0, r1, r2, r3;
                {
                    float2 f0 = *reinterpret_cast<float2*>(&acc2[pj][0]);
                    float2 f1 = *reinterpret_cast<float2*>(&acc2[pj][1]);
                    float2 f2 = *reinterpret_cast<float2*>(&acc2[pj][2]);
                    float2 f3 = *reinterpret_cast<float2*>(&acc2[pj][3]);
                    r0 = f0.x + f0.y; r1 = f1.x + f1.y;
                    r2 = f2.x + f2.y; r3 = f3.x + f3.y;
                }
                float* dst = out + (size_t)rr[pj] * COUT + c0;   // 16B aligned
                asm volatile("red.global.add.v4.f32 [%0], {%1, %2, %3, %4};"
                             :: "l"(dst), "f"(r0), "f"(r1), "f"(r2), "f"(r3)
                             : "memory");
            }
        }

        asm volatile("cp.async.wait_group 0;\n" ::: "memory");
        __syncthreads();      // done reading Wbuf[buf]; next W ready
        buf ^= 1;
    }
}

extern "C" void kernel_launch(void* const* d_in, const int* in_sizes, int n_in,
                              void* d_out, int out_size) {
    const float* feats     = (const float*)d_in[0];   // [N, 64]
    const float* weight    = (const float*)d_in[1];   // [KV, 64, 64]
    const float* bias      = (const float*)d_in[2];   // [64]
    const int*   out_index = (const int*)d_in[3];     // [KV, N]
    float* out = (float*)d_out;                        // [n_out, 64]

    int N  = in_sizes[0] / CIN;
    int KV = in_sizes[1] / (COUT * CIN);

    // 1) out = bias (broadcast)
    int total4 = out_size / 4;
    int ib = (total4 + 255) / 256;
    bias_init_kernel<<<ib, 256>>>((float4*)out, (const float4*)bias, total4);

    // 2) persistent-over-k GEMM + scatter-add
    const int smem_bytes = (TILE_N * CIN + 2 * COUT * CIN) * sizeof(float);  // 64KB
    cudaFuncSetAttribute(spconvt_gemm_scatter_kernel,
                         cudaFuncAttributeMaxDynamicSharedMemorySize, smem_bytes);
    dim3 grid((N + TILE_N - 1) / TILE_N, (KV + KCHUNK - 1) / KCHUNK);
    spconvt_gemm_scatter_kernel<<<grid, 256, smem_bytes>>>(
        feats, weight, out_index, out, N, KV);
}